// round 11
// baseline (speedup 1.0000x reference)
#include <cuda_runtime.h>
#include <cstdint>

#define NQ 20
#define BATCH 4

__device__ float2 g_state[(size_t)BATCH << NQ];
__device__ float2 g_mats[19][16];

__device__ __forceinline__ float2 cmul(float2 a, float2 b){
    return make_float2(a.x*b.x - a.y*b.y, a.x*b.y + a.y*b.x);
}
__device__ __forceinline__ float2 cadd(float2 a, float2 b){
    return make_float2(a.x + b.x, a.y + b.y);
}
__device__ void mul22(const float2* A, const float2* B, float2* C){
    for (int i = 0; i < 2; i++) for (int j = 0; j < 2; j++){
        float2 s = make_float2(0.f,0.f);
        for (int k = 0; k < 2; k++) s = cadd(s, cmul(A[i*2+k], B[k*2+j]));
        C[i*2+j] = s;
    }
}
__device__ void mul44(const float2* A, const float2* B, float2* C){
    for (int i = 0; i < 4; i++) for (int j = 0; j < 4; j++){
        float2 s = make_float2(0.f,0.f);
        for (int k = 0; k < 4; k++) s = cadd(s, cmul(A[i*4+k], B[k*4+j]));
        C[i*4+j] = s;
    }
}
// A = factor on qubit g (higher flat bit)
__device__ void kron22(const float2* A, const float2* B, float2* K){
    for (int ia=0; ia<2; ia++) for (int ib=0; ib<2; ib++)
        for (int ja=0; ja<2; ja++) for (int jb=0; jb<2; jb++)
            K[(ia*2+ib)*4 + (ja*2+jb)] = cmul(A[ia*2+ja], B[ib*2+jb]);
}
__device__ void id2(float2* M){
    M[0]=make_float2(1.f,0.f); M[1]=make_float2(0.f,0.f);
    M[2]=make_float2(0.f,0.f); M[3]=make_float2(1.f,0.f);
}
// U = Rz*Ry*Rx, half-angles pre-scaled by HM
__device__ void fused1q(const float* w, int off, float HM, float2* U){
    float hx=w[off]*HM, hy=w[off+1]*HM, hz=w[off+2]*HM;
    float cx=cosf(hx), sx=sinf(hx), cy=cosf(hy), sy=sinf(hy), cz=cosf(hz), sz=sinf(hz);
    float2 RX[4] = { {cx,0.f},{0.f,-sx},{0.f,-sx},{cx,0.f} };
    float2 RY[4] = { {cy,0.f},{-sy,0.f},{sy,0.f},{cy,0.f} };
    float2 RZ[4] = { {cz,-sz},{0.f,0.f},{0.f,0.f},{cz,sz} };
    float2 T[4]; mul22(RY, RX, T); mul22(RZ, T, U);
}

// fused[g] = (P (x) Q) * Rzz*Ryy*Rxx * (R (x) S)
// R = L1[0] iff g==0 ; S = L1[g+1] ; P = L2[g] iff g>=10 ; Q = L2[19] iff g==18
// (L2[0..9] act only on traced-out bits -> dropped exactly)
__global__ void build_gates_kernel(const float* __restrict__ w){
    int g = threadIdx.x;
    if (g >= 19) return;
    const float HM = 0.5f * 0.63245553203367586f;  // 0.5 * W_MUL

    float2 S[4]; fused1q(w, 3*(g+1), HM, S);
    float2 R[4]; if (g == 0)  fused1q(w, 0,        HM, R); else id2(R);
    float2 P[4]; if (g >= 10) fused1q(w, 117+3*g,  HM, P); else id2(P);
    float2 Q[4]; if (g == 18) fused1q(w, 174,      HM, Q); else id2(Q);

    float ha=w[60+3*g]*HM, hb=w[61+3*g]*HM, hc=w[62+3*g]*HM;
    float ca=cosf(ha), sa=sinf(ha), cb=cosf(hb), sb=sinf(hb), cc=cosf(hc), sc=sinf(hc);

    float2 XXm[16], YYm[16], ZZm[16];
    for (int i=0;i<16;i++){ XXm[i]=YYm[i]=ZZm[i]=make_float2(0.f,0.f); }
    XXm[0]=XXm[5]=XXm[10]=XXm[15]=make_float2(ca,0.f);
    XXm[3]=XXm[6]=XXm[9]=XXm[12]=make_float2(0.f,-sa);
    YYm[0]=YYm[5]=YYm[10]=YYm[15]=make_float2(cb,0.f);
    YYm[3]=make_float2(0.f,sb);  YYm[6]=make_float2(0.f,-sb);
    YYm[9]=make_float2(0.f,-sb); YYm[12]=make_float2(0.f,sb);
    ZZm[0]=make_float2(cc,-sc); ZZm[5]=make_float2(cc,sc);
    ZZm[10]=make_float2(cc,sc); ZZm[15]=make_float2(cc,-sc);

    float2 T[16], G[16], L4[16], R4[16], T2[16], F[16];
    mul44(YYm, XXm, T); mul44(ZZm, T, G);
    kron22(P, Q, L4);   kron22(R, S, R4);
    mul44(L4, G, T2);   mul44(T2, R4, F);
    for (int i=0;i<16;i++) g_mats[g][i] = F[i];
}

// ---- shared-memory gate machinery: 4096-complex tile, 256 threads ----
__device__ __forceinline__ int swz(int e){ return e ^ ((e >> 5) & 31); }
__host__ __device__ constexpr int partner5(int b){ return b < 5 ? b + 5 : b - 5; }
__host__ __device__ constexpr int lane_bit(int P, int r){
    return (P % 5 == r) ? partner5(P)
         : (((P + 1) % 5 == r) ? partner5(P + 1) : r);
}
__host__ __device__ constexpr int nth_set(unsigned mask, int k){
    int c = 0;
    for (int b = 0; b < 16; b++)
        if ((mask >> b) & 1){ if (c == k) return b; c++; }
    return 0;
}
__device__ __forceinline__ float2 row4(const float2* m, float2 a0, float2 a1,
                                       float2 a2, float2 a3){
    float2 r = cmul(m[0], a0);
    r = cadd(r, cmul(m[1], a1));
    r = cadd(r, cmul(m[2], a2));
    r = cadd(r, cmul(m[3], a3));
    return r;
}
// 4x4 gate on tile-bit pair (P+1, P); matrix col index = 2*bit(P+1)+bit(P)
template<int P>
__device__ __forceinline__ void apply_gate(float2* sm, const float2* __restrict__ gm){
    constexpr int LB0=lane_bit(P,0), LB1=lane_bit(P,1), LB2=lane_bit(P,2),
                  LB3=lane_bit(P,3), LB4=lane_bit(P,4);
    constexpr unsigned lmask = (1u<<LB0)|(1u<<LB1)|(1u<<LB2)|(1u<<LB3)|(1u<<LB4);
    constexpr unsigned omask = 0xFFFu & ~lmask & ~(3u << P);
    constexpr int O0=nth_set(omask,0), O1=nth_set(omask,1), O2=nth_set(omask,2),
                  O3=nth_set(omask,3), O4=nth_set(omask,4);
    float2 m[16];
#pragma unroll
    for (int i=0;i<16;i++) m[i] = gm[i];
    const int lane = threadIdx.x & 31, wrp = threadIdx.x >> 5;
    const int jl = ((lane&1)<<LB0) | (((lane>>1)&1)<<LB1) | (((lane>>2)&1)<<LB2)
                 | (((lane>>3)&1)<<LB3) | (((lane>>4)&1)<<LB4);
#pragma unroll
    for (int it=0; it<4; it++){
        int go = wrp*4 + it;
        int jo = ((go&1)<<O0) | (((go>>1)&1)<<O1) | (((go>>2)&1)<<O2)
               | (((go>>3)&1)<<O3) | (((go>>4)&1)<<O4);
        int j = jl | jo;
        int e0=swz(j), e1=swz(j|(1<<P)), e2=swz(j|(2<<P)), e3=swz(j|(3<<P));
        float2 a0=sm[e0], a1=sm[e1], a2=sm[e2], a3=sm[e3];
        float2 r0=row4(m+0,a0,a1,a2,a3), r1=row4(m+4,a0,a1,a2,a3);
        float2 r2=row4(m+8,a0,a1,a2,a3), r3=row4(m+12,a0,a1,a2,a3);
        sm[e0]=r0; sm[e1]=r1; sm[e2]=r2; sm[e3]=r3;
    }
}

// Pass 1: gates 0..6 (global bit pairs (19,18)..(13,12)). Tile: u[0..3]=g[0..3],
// u[4..11]=g[12..19]; fixed g[4..11]=F. Local P = 10-g. Converts input to complex.
__global__ void pass1_kernel(const float* __restrict__ x){
    __shared__ float2 sm[4096];
    const int F = blockIdx.x, b = blockIdx.y, tid = threadIdx.x;
    const float* xb = x + ((size_t)b << NQ);
    float2* st = g_state + ((size_t)b << NQ);
#pragma unroll
    for (int it=0; it<16; it++){
        int u = it*256 + tid;
        int gi = ((u>>4)<<12) | (F<<4) | (u&15);
        sm[swz(u)] = make_float2(xb[gi], 0.0f);
    }
    __syncthreads();
    apply_gate<10>(sm, g_mats[0]); __syncthreads();
    apply_gate< 9>(sm, g_mats[1]); __syncthreads();
    apply_gate< 8>(sm, g_mats[2]); __syncthreads();
    apply_gate< 7>(sm, g_mats[3]); __syncthreads();
    apply_gate< 6>(sm, g_mats[4]); __syncthreads();
    apply_gate< 5>(sm, g_mats[5]); __syncthreads();
    apply_gate< 4>(sm, g_mats[6]); __syncthreads();
#pragma unroll
    for (int it=0; it<16; it++){
        int u = it*256 + tid;
        int gi = ((u>>4)<<12) | (F<<4) | (u&15);
        st[gi] = sm[swz(u)];
    }
}

// Pass 2: gates 7..12 (pairs (12,11)..(7,6)). Tile: u[0..4]=g[0..4],
// u[5..11]=g[6..12]; fixed g5=F&1, g[13..19]=F>>1. Local P = 17-g.
__global__ void pass2_kernel(){
    __shared__ float2 sm[4096];
    const int F = blockIdx.x, b = blockIdx.y, tid = threadIdx.x;
    float2* st = g_state + ((size_t)b << NQ);
#pragma unroll
    for (int it=0; it<16; it++){
        int u = it*256 + tid;
        int gi = ((F>>1)<<13) | (((u>>5)&127)<<6) | ((F&1)<<5) | (u&31);
        sm[swz(u)] = st[gi];
    }
    __syncthreads();
    apply_gate<10>(sm, g_mats[7]);  __syncthreads();
    apply_gate< 9>(sm, g_mats[8]);  __syncthreads();
    apply_gate< 8>(sm, g_mats[9]);  __syncthreads();
    apply_gate< 7>(sm, g_mats[10]); __syncthreads();
    apply_gate< 6>(sm, g_mats[11]); __syncthreads();
    apply_gate< 5>(sm, g_mats[12]); __syncthreads();
#pragma unroll
    for (int it=0; it<16; it++){
        int u = it*256 + tid;
        int gi = ((F>>1)<<13) | (((u>>5)&127)<<6) | ((F&1)<<5) | (u&31);
        st[gi] = sm[swz(u)];
    }
}

// Pass 3: gates 13..18 (pairs (6,5)..(1,0)). Tile = global bits 0..11. Local P = 18-g.
__global__ void pass3_kernel(){
    __shared__ float2 sm[4096];
    const int F = blockIdx.x, b = blockIdx.y, tid = threadIdx.x;
    float2* st = g_state + ((size_t)b << NQ) + ((size_t)F << 12);
#pragma unroll
    for (int it=0; it<16; it++){ int u = it*256+tid; sm[swz(u)] = st[u]; }
    __syncthreads();
    apply_gate<5>(sm, g_mats[13]); __syncthreads();
    apply_gate<4>(sm, g_mats[14]); __syncthreads();
    apply_gate<3>(sm, g_mats[15]); __syncthreads();
    apply_gate<2>(sm, g_mats[16]); __syncthreads();
    apply_gate<1>(sm, g_mats[17]); __syncthreads();
    apply_gate<0>(sm, g_mats[18]); __syncthreads();
#pragma unroll
    for (int it=0; it<16; it++){ int u = it*256+tid; st[u] = sm[swz(u)]; }
}

// ---- RDM: rdm[b,a,c] = sum_t psi[b,t*1024+a]*conj(psi[b,t*1024+c]) ----
// 128x128 complex tiles, upper-triangle pairs only; packed fma.rn.f32x2.
#define SPLAT2(d, f) asm("mov.b64 %0, {%1, %1};" : "=l"(d) : "r"(__float_as_uint(f)))
#define FMA2(d, a, b) asm("fma.rn.f32x2 %0, %1, %2, %0;" : "+l"(d) : "l"(a), "l"(b))

__global__ void __launch_bounds__(256, 1) rdm_kernel(float2* __restrict__ out){
    __shared__ __align__(16) float2 As [16][128];  // (ar, ai)
    __shared__ __align__(16) float2 Cs1[16][128];  // (br, -bi)
    __shared__ __align__(16) float2 Cs2[16][128];  // (bi,  br)

    int p = blockIdx.x, ta = 0;
    const int b = blockIdx.y;
    while (p >= 8 - ta){ p -= 8 - ta; ta++; }
    const int tc = ta + p;

    const float2* Ab = g_state + ((size_t)b << NQ);
    const int aBase = ta*128, cBase = tc*128;
    const int tid = threadIdx.x, tx = tid & 15, ty = tid >> 4;
    const int lr = tid >> 6, lc = (tid & 63) * 2;

    unsigned long long acc[8][8];
#pragma unroll
    for (int i=0;i<8;i++)
#pragma unroll
        for (int j=0;j<8;j++) acc[i][j] = 0ull;

    for (int k0 = 0; k0 < 1024; k0 += 16){
        __syncthreads();
#pragma unroll
        for (int t=0; t<4; t++){
            int r = lr + t*4;
            const float2* row = Ab + (size_t)(k0 + r) * 1024;
            float4 va = *(const float4*)&row[aBase + lc];
            float4 vc = *(const float4*)&row[cBase + lc];
            *(float4*)&As [r][lc] = va;
            *(float4*)&Cs1[r][lc] = make_float4(vc.x, -vc.y, vc.z, -vc.w);
            *(float4*)&Cs2[r][lc] = make_float4(vc.y,  vc.x, vc.w,  vc.z);
        }
        __syncthreads();
#pragma unroll
        for (int k=0; k<16; k++){
            unsigned long long av[8], c1v[8], c2v[8];
#pragma unroll
            for (int i=0;i<4;i++){
                *(float4*)&av [i*2] = *(const float4*)&As [k][2*ty + 32*i];
                *(float4*)&c1v[i*2] = *(const float4*)&Cs1[k][2*tx + 32*i];
                *(float4*)&c2v[i*2] = *(const float4*)&Cs2[k][2*tx + 32*i];
            }
#pragma unroll
            for (int r=0;r<8;r++){
                float2 a = *(float2*)&av[r];
                unsigned long long sr, si;
                SPLAT2(sr, a.x); SPLAT2(si, a.y);
#pragma unroll
                for (int c=0;c<8;c++){
                    FMA2(acc[r][c], sr, c1v[c]);
                    FMA2(acc[r][c], si, c2v[c]);
                }
            }
        }
    }

    const size_t ob = (size_t)b << NQ;
#pragma unroll
    for (int r=0;r<8;r++){
        int row = aBase + 2*ty + 32*(r>>1) + (r&1);
#pragma unroll
        for (int c=0;c<8;c++){
            int col = cBase + 2*tx + 32*(c>>1) + (c&1);
            float2 v = *(float2*)&acc[r][c];
            out[ob + (size_t)row*1024 + col] = v;
            if (ta != tc)
                out[ob + (size_t)col*1024 + row] = make_float2(v.x, -v.y);
        }
    }
}

extern "C" void kernel_launch(void* const* d_in, const int* in_sizes, int n_in,
                              void* d_out, int out_size) {
    const float* x = (const float*)d_in[0];      // (4, 1, 2^20) float32
    const float* w = (const float*)d_in[1];      // (177,) float32
    float2* out = (float2*)d_out;                // (4,1024,1024,2) float32

    build_gates_kernel<<<1, 32>>>(w);
    pass1_kernel<<<dim3(256, BATCH), 256>>>(x);
    pass2_kernel<<<dim3(256, BATCH), 256>>>();
    pass3_kernel<<<dim3(256, BATCH), 256>>>();
    rdm_kernel<<<dim3(36, BATCH), 256>>>(out);
}

// round 13
// speedup vs baseline: 1.0377x; 1.0377x over previous
#include <cuda_runtime.h>
#include <cstdint>

#define NQ 20
#define BATCH 4

__device__ float2 g_state[(size_t)BATCH << NQ];
__device__ float2 g_mats[19][16];

__device__ __forceinline__ float2 cmul(float2 a, float2 b){
    return make_float2(a.x*b.x - a.y*b.y, a.x*b.y + a.y*b.x);
}
__device__ __forceinline__ float2 cadd(float2 a, float2 b){
    return make_float2(a.x + b.x, a.y + b.y);
}
__device__ void mul22(const float2* A, const float2* B, float2* C){
    for (int i = 0; i < 2; i++) for (int j = 0; j < 2; j++){
        float2 s = make_float2(0.f,0.f);
        for (int k = 0; k < 2; k++) s = cadd(s, cmul(A[i*2+k], B[k*2+j]));
        C[i*2+j] = s;
    }
}
__device__ void mul44(const float2* A, const float2* B, float2* C){
    for (int i = 0; i < 4; i++) for (int j = 0; j < 4; j++){
        float2 s = make_float2(0.f,0.f);
        for (int k = 0; k < 4; k++) s = cadd(s, cmul(A[i*4+k], B[k*4+j]));
        C[i*4+j] = s;
    }
}
// A = factor on qubit g (higher flat bit)
__device__ void kron22(const float2* A, const float2* B, float2* K){
    for (int ia=0; ia<2; ia++) for (int ib=0; ib<2; ib++)
        for (int ja=0; ja<2; ja++) for (int jb=0; jb<2; jb++)
            K[(ia*2+ib)*4 + (ja*2+jb)] = cmul(A[ia*2+ja], B[ib*2+jb]);
}
__device__ void id2(float2* M){
    M[0]=make_float2(1.f,0.f); M[1]=make_float2(0.f,0.f);
    M[2]=make_float2(0.f,0.f); M[3]=make_float2(1.f,0.f);
}
// U = Rz*Ry*Rx, half-angles pre-scaled by HM
__device__ void fused1q(const float* w, int off, float HM, float2* U){
    float hx=w[off]*HM, hy=w[off+1]*HM, hz=w[off+2]*HM;
    float cx=cosf(hx), sx=sinf(hx), cy=cosf(hy), sy=sinf(hy), cz=cosf(hz), sz=sinf(hz);
    float2 RX[4] = { {cx,0.f},{0.f,-sx},{0.f,-sx},{cx,0.f} };
    float2 RY[4] = { {cy,0.f},{-sy,0.f},{sy,0.f},{cy,0.f} };
    float2 RZ[4] = { {cz,-sz},{0.f,0.f},{0.f,0.f},{cz,sz} };
    float2 T[4]; mul22(RY, RX, T); mul22(RZ, T, U);
}

// fused[g] = (P (x) Q) * Rzz*Ryy*Rxx * (R (x) S)
// R = L1[0] iff g==0 ; S = L1[g+1] ; P = L2[g] iff g>=10 ; Q = L2[19] iff g==18
// (L2[0..9] act only on traced-out bits -> dropped exactly)
__global__ void build_gates_kernel(const float* __restrict__ w){
    int g = threadIdx.x;
    if (g >= 19) return;
    const float HM = 0.5f * 0.63245553203367586f;  // 0.5 * W_MUL

    float2 S[4]; fused1q(w, 3*(g+1), HM, S);
    float2 R[4]; if (g == 0)  fused1q(w, 0,        HM, R); else id2(R);
    float2 P[4]; if (g >= 10) fused1q(w, 117+3*g,  HM, P); else id2(P);
    float2 Q[4]; if (g == 18) fused1q(w, 174,      HM, Q); else id2(Q);

    float ha=w[60+3*g]*HM, hb=w[61+3*g]*HM, hc=w[62+3*g]*HM;
    float ca=cosf(ha), sa=sinf(ha), cb=cosf(hb), sb=sinf(hb), cc=cosf(hc), sc=sinf(hc);

    float2 XXm[16], YYm[16], ZZm[16];
    for (int i=0;i<16;i++){ XXm[i]=YYm[i]=ZZm[i]=make_float2(0.f,0.f); }
    XXm[0]=XXm[5]=XXm[10]=XXm[15]=make_float2(ca,0.f);
    XXm[3]=XXm[6]=XXm[9]=XXm[12]=make_float2(0.f,-sa);
    YYm[0]=YYm[5]=YYm[10]=YYm[15]=make_float2(cb,0.f);
    YYm[3]=make_float2(0.f,sb);  YYm[6]=make_float2(0.f,-sb);
    YYm[9]=make_float2(0.f,-sb); YYm[12]=make_float2(0.f,sb);
    ZZm[0]=make_float2(cc,-sc); ZZm[5]=make_float2(cc,sc);
    ZZm[10]=make_float2(cc,sc); ZZm[15]=make_float2(cc,-sc);

    float2 T[16], G[16], L4[16], R4[16], T2[16], F[16];
    mul44(YYm, XXm, T); mul44(ZZm, T, G);
    kron22(P, Q, L4);   kron22(R, S, R4);
    mul44(L4, G, T2);   mul44(T2, R4, F);
    for (int i=0;i<16;i++) g_mats[g][i] = F[i];
}

// ---- shared-memory gate machinery: 4096-complex tile, 256 threads ----
__device__ __forceinline__ int swz(int e){ return e ^ ((e >> 5) & 31); }
__host__ __device__ constexpr int partner5(int b){ return b < 5 ? b + 5 : b - 5; }
__host__ __device__ constexpr int lane_bit(int P, int r){
    return (P % 5 == r) ? partner5(P)
         : (((P + 1) % 5 == r) ? partner5(P + 1) : r);
}
__host__ __device__ constexpr int nth_set(unsigned mask, int k){
    int c = 0;
    for (int b = 0; b < 16; b++)
        if ((mask >> b) & 1){ if (c == k) return b; c++; }
    return 0;
}
__device__ __forceinline__ float2 row4(const float2* m, float2 a0, float2 a1,
                                       float2 a2, float2 a3){
    float2 r = cmul(m[0], a0);
    r = cadd(r, cmul(m[1], a1));
    r = cadd(r, cmul(m[2], a2));
    r = cadd(r, cmul(m[3], a3));
    return r;
}
// 4x4 gate on tile-bit pair (P+1, P); matrix col index = 2*bit(P+1)+bit(P)
template<int P>
__device__ __forceinline__ void apply_gate(float2* sm, const float2* __restrict__ gm){
    constexpr int LB0=lane_bit(P,0), LB1=lane_bit(P,1), LB2=lane_bit(P,2),
                  LB3=lane_bit(P,3), LB4=lane_bit(P,4);
    constexpr unsigned lmask = (1u<<LB0)|(1u<<LB1)|(1u<<LB2)|(1u<<LB3)|(1u<<LB4);
    constexpr unsigned omask = 0xFFFu & ~lmask & ~(3u << P);
    constexpr int O0=nth_set(omask,0), O1=nth_set(omask,1), O2=nth_set(omask,2),
                  O3=nth_set(omask,3), O4=nth_set(omask,4);
    float2 m[16];
#pragma unroll
    for (int i=0;i<16;i++) m[i] = gm[i];
    const int lane = threadIdx.x & 31, wrp = threadIdx.x >> 5;
    const int jl = ((lane&1)<<LB0) | (((lane>>1)&1)<<LB1) | (((lane>>2)&1)<<LB2)
                 | (((lane>>3)&1)<<LB3) | (((lane>>4)&1)<<LB4);
#pragma unroll
    for (int it=0; it<4; it++){
        int go = wrp*4 + it;
        int jo = ((go&1)<<O0) | (((go>>1)&1)<<O1) | (((go>>2)&1)<<O2)
               | (((go>>3)&1)<<O3) | (((go>>4)&1)<<O4);
        int j = jl | jo;
        int e0=swz(j), e1=swz(j|(1<<P)), e2=swz(j|(2<<P)), e3=swz(j|(3<<P));
        float2 a0=sm[e0], a1=sm[e1], a2=sm[e2], a3=sm[e3];
        float2 r0=row4(m+0,a0,a1,a2,a3), r1=row4(m+4,a0,a1,a2,a3);
        float2 r2=row4(m+8,a0,a1,a2,a3), r3=row4(m+12,a0,a1,a2,a3);
        sm[e0]=r0; sm[e1]=r1; sm[e2]=r2; sm[e3]=r3;
    }
}

// Pass 1: gates 0..6 (global bit pairs (19,18)..(13,12)). Tile: u[0..3]=g[0..3],
// u[4..11]=g[12..19]; fixed g[4..11]=F. Local P = 10-g. Converts input to complex.
__global__ void pass1_kernel(const float* __restrict__ x){
    __shared__ float2 sm[4096];
    const int F = blockIdx.x, b = blockIdx.y, tid = threadIdx.x;
    const float* xb = x + ((size_t)b << NQ);
    float2* st = g_state + ((size_t)b << NQ);
#pragma unroll
    for (int it=0; it<16; it++){
        int u = it*256 + tid;
        int gi = ((u>>4)<<12) | (F<<4) | (u&15);
        sm[swz(u)] = make_float2(xb[gi], 0.0f);
    }
    __syncthreads();
    apply_gate<10>(sm, g_mats[0]); __syncthreads();
    apply_gate< 9>(sm, g_mats[1]); __syncthreads();
    apply_gate< 8>(sm, g_mats[2]); __syncthreads();
    apply_gate< 7>(sm, g_mats[3]); __syncthreads();
    apply_gate< 6>(sm, g_mats[4]); __syncthreads();
    apply_gate< 5>(sm, g_mats[5]); __syncthreads();
    apply_gate< 4>(sm, g_mats[6]); __syncthreads();
#pragma unroll
    for (int it=0; it<16; it++){
        int u = it*256 + tid;
        int gi = ((u>>4)<<12) | (F<<4) | (u&15);
        st[gi] = sm[swz(u)];
    }
}

// Pass 2: gates 7..12 (pairs (12,11)..(7,6)). Tile: u[0..4]=g[0..4],
// u[5..11]=g[6..12]; fixed g5=F&1, g[13..19]=F>>1. Local P = 17-g.
__global__ void pass2_kernel(){
    __shared__ float2 sm[4096];
    const int F = blockIdx.x, b = blockIdx.y, tid = threadIdx.x;
    float2* st = g_state + ((size_t)b << NQ);
#pragma unroll
    for (int it=0; it<16; it++){
        int u = it*256 + tid;
        int gi = ((F>>1)<<13) | (((u>>5)&127)<<6) | ((F&1)<<5) | (u&31);
        sm[swz(u)] = st[gi];
    }
    __syncthreads();
    apply_gate<10>(sm, g_mats[7]);  __syncthreads();
    apply_gate< 9>(sm, g_mats[8]);  __syncthreads();
    apply_gate< 8>(sm, g_mats[9]);  __syncthreads();
    apply_gate< 7>(sm, g_mats[10]); __syncthreads();
    apply_gate< 6>(sm, g_mats[11]); __syncthreads();
    apply_gate< 5>(sm, g_mats[12]); __syncthreads();
#pragma unroll
    for (int it=0; it<16; it++){
        int u = it*256 + tid;
        int gi = ((F>>1)<<13) | (((u>>5)&127)<<6) | ((F&1)<<5) | (u&31);
        st[gi] = sm[swz(u)];
    }
}

// Pass 3: gates 13..18 (pairs (6,5)..(1,0)). Tile = global bits 0..11. Local P = 18-g.
__global__ void pass3_kernel(){
    __shared__ float2 sm[4096];
    const int F = blockIdx.x, b = blockIdx.y, tid = threadIdx.x;
    float2* st = g_state + ((size_t)b << NQ) + ((size_t)F << 12);
#pragma unroll
    for (int it=0; it<16; it++){ int u = it*256+tid; sm[swz(u)] = st[u]; }
    __syncthreads();
    apply_gate<5>(sm, g_mats[13]); __syncthreads();
    apply_gate<4>(sm, g_mats[14]); __syncthreads();
    apply_gate<3>(sm, g_mats[15]); __syncthreads();
    apply_gate<2>(sm, g_mats[16]); __syncthreads();
    apply_gate<1>(sm, g_mats[17]); __syncthreads();
    apply_gate<0>(sm, g_mats[18]); __syncthreads();
#pragma unroll
    for (int it=0; it<16; it++){ int u = it*256+tid; st[u] = sm[swz(u)]; }
}

// ---- RDM: rdm[b,a,c] = sum_t psi[b,t*1024+a]*conj(psi[b,t*1024+c]) ----
// 128x128 complex tiles, upper-triangle pairs only; packed fma.rn.f32x2.
// Software-pipelined: 8-row k-chunks, double-buffered smem, LDG prefetch
// into registers overlapped with the FMA2 compute of the previous chunk.
#define SPLAT2(d, f) asm("mov.b64 %0, {%1, %1};" : "=l"(d) : "r"(__float_as_uint(f)))
#define FMA2(d, a, b) asm("fma.rn.f32x2 %0, %1, %2, %0;" : "+l"(d) : "l"(a), "l"(b))

__global__ void __launch_bounds__(256, 1) rdm_kernel(float2* __restrict__ out){
    __shared__ __align__(16) float2 As [2][8][128];  // (ar, ai)
    __shared__ __align__(16) float2 Cs1[2][8][128];  // (br, -bi)
    __shared__ __align__(16) float2 Cs2[2][8][128];  // (bi,  br)

    int p = blockIdx.x, ta = 0;
    const int b = blockIdx.y;
    while (p >= 8 - ta){ p -= 8 - ta; ta++; }
    const int tc = ta + p;

    const float2* Ab = g_state + ((size_t)b << NQ);
    const int aBase = ta*128, cBase = tc*128;
    const int tid = threadIdx.x, tx = tid & 15, ty = tid >> 4;
    const int lr = tid >> 6, lc = (tid & 63) * 2;   // rows lr, lr+4 ; float2 col lc

    unsigned long long acc[8][8];
#pragma unroll
    for (int i=0;i<8;i++)
#pragma unroll
        for (int j=0;j<8;j++) acc[i][j] = 0ull;

    float4 pa[2], pc[2];   // prefetch registers (2 rows x 2 float2 each)

    // prologue: load chunk 0, store to stage 0
#pragma unroll
    for (int t=0; t<2; t++){
        const float2* row = Ab + (size_t)(lr + 4*t) * 1024;
        pa[t] = *(const float4*)&row[aBase + lc];
        pc[t] = *(const float4*)&row[cBase + lc];
    }
#pragma unroll
    for (int t=0; t<2; t++){
        int r = lr + 4*t;
        *(float4*)&As [0][r][lc] = pa[t];
        *(float4*)&Cs1[0][r][lc] = make_float4(pc[t].x, -pc[t].y, pc[t].z, -pc[t].w);
        *(float4*)&Cs2[0][r][lc] = make_float4(pc[t].y,  pc[t].x, pc[t].w,  pc[t].z);
    }
    __syncthreads();

    for (int ch = 0; ch < 128; ch++){
        const int cur = ch & 1;
        // issue next chunk's global loads early (hidden under compute)
        if (ch + 1 < 128){
#pragma unroll
            for (int t=0; t<2; t++){
                const float2* row = Ab + (size_t)((ch+1)*8 + lr + 4*t) * 1024;
                pa[t] = *(const float4*)&row[aBase + lc];
                pc[t] = *(const float4*)&row[cBase + lc];
            }
        }
        // compute 8 k-steps on stage cur
#pragma unroll
        for (int k=0; k<8; k++){
            unsigned long long av[8], c1v[8], c2v[8];
#pragma unroll
            for (int i=0;i<4;i++){
                *(float4*)&av [i*2] = *(const float4*)&As [cur][k][2*ty + 32*i];
                *(float4*)&c1v[i*2] = *(const float4*)&Cs1[cur][k][2*tx + 32*i];
                *(float4*)&c2v[i*2] = *(const float4*)&Cs2[cur][k][2*tx + 32*i];
            }
#pragma unroll
            for (int r=0;r<8;r++){
                float2 a = *(float2*)&av[r];
                unsigned long long sr, si;
                SPLAT2(sr, a.x); SPLAT2(si, a.y);
#pragma unroll
                for (int c=0;c<8;c++){
                    FMA2(acc[r][c], sr, c1v[c]);
                    FMA2(acc[r][c], si, c2v[c]);
                }
            }
        }
        // store prefetched chunk into the other stage (its readers finished
        // at the barrier ending iteration ch-1), then barrier
        if (ch + 1 < 128){
            const int nxt = 1 - cur;
#pragma unroll
            for (int t=0; t<2; t++){
                int r = lr + 4*t;
                *(float4*)&As [nxt][r][lc] = pa[t];
                *(float4*)&Cs1[nxt][r][lc] = make_float4(pc[t].x, -pc[t].y, pc[t].z, -pc[t].w);
                *(float4*)&Cs2[nxt][r][lc] = make_float4(pc[t].y,  pc[t].x, pc[t].w,  pc[t].z);
            }
        }
        __syncthreads();
    }

    const size_t ob = (size_t)b << NQ;
#pragma unroll
    for (int r=0;r<8;r++){
        int row = aBase + 2*ty + 32*(r>>1) + (r&1);
#pragma unroll
        for (int c=0;c<8;c++){
            int col = cBase + 2*tx + 32*(c>>1) + (c&1);
            float2 v = *(float2*)&acc[r][c];
            out[ob + (size_t)row*1024 + col] = v;
            if (ta != tc)
                out[ob + (size_t)col*1024 + row] = make_float2(v.x, -v.y);
        }
    }
}

extern "C" void kernel_launch(void* const* d_in, const int* in_sizes, int n_in,
                              void* d_out, int out_size) {
    const float* x = (const float*)d_in[0];      // (4, 1, 2^20) float32
    const float* w = (const float*)d_in[1];      // (177,) float32
    float2* out = (float2*)d_out;                // (4,1024,1024,2) float32

    build_gates_kernel<<<1, 32>>>(w);
    pass1_kernel<<<dim3(256, BATCH), 256>>>(x);
    pass2_kernel<<<dim3(256, BATCH), 256>>>();
    pass3_kernel<<<dim3(256, BATCH), 256>>>();
    rdm_kernel<<<dim3(36, BATCH), 256>>>(out);
}